// round 9
// baseline (speedup 1.0000x reference)
#include <cuda_runtime.h>
#include <math.h>

#define BB 4096
#define NN 64

// Per-CTA (half-batch: 32 query tokens) smem layout (floats), 104,960 bytes:
//  sh_h [32][260] = 8320
//  sh_z [32][20]  = 640
//  sh_c [32][132] = 4224
//  sq   [32][68]  = 2176   (alias: clat after C1)
//  sk   [64][68]  = 4352   (alias: sred in D)
//  sv   [64][68]  = 4352
//  sat  [32][68]  = 2176   (alias: gate/cand in D/E)
#define OFF_H   0
#define OFF_Z   8320
#define OFF_C   8960
#define OFF_Q   13184
#define OFF_K   15360
#define OFF_V   19712
#define OFF_AT  24064
#define SMEM_FLOATS 26240

typedef unsigned long long ull;

__device__ __forceinline__ ull pk(float a, float b) {
    ull r; asm("mov.b64 %0, {%1, %2};" : "=l"(r) : "f"(a), "f"(b)); return r;
}
__device__ __forceinline__ void upk(ull v, float& a, float& b) {
    asm("mov.b64 {%0, %1}, %2;" : "=f"(a), "=f"(b) : "l"(v));
}
#define FMAX2(acc, a, b) asm("fma.rn.f32x2 %0, %1, %2, %0;" : "+l"(acc) : "l"(a), "l"(b))

__device__ __forceinline__ float wsum32(float v) {
    #pragma unroll
    for (int m = 16; m > 0; m >>= 1) v += __shfl_xor_sync(0xffffffffu, v, m);
    return v;
}
__device__ __forceinline__ float wmax32(float v) {
    #pragma unroll
    for (int m = 16; m > 0; m >>= 1) v = fmaxf(v, __shfl_xor_sync(0xffffffffu, v, m));
    return v;
}

// Phase-D inner: 2 tokens (delta-8 rows, smem x) x 16 outputs over n4*4 k-rows; w via LDG.
__device__ __forceinline__ void d_accum(const float* __restrict__ x0, int xs,
                                        const float* __restrict__ wsel, int ibase,
                                        int n4, int j4, ull acc[2][2]) {
    for (int s = 0; s < n4; s++) {
        const int il = s << 2;
        float4 xa = *reinterpret_cast<const float4*>(x0 + il);
        float4 xb = *reinterpret_cast<const float4*>(x0 + 8 * xs + il);
        const float4* wr = reinterpret_cast<const float4*>(wsel + (ibase + il) * 16) + j4;
        #pragma unroll
        for (int r = 0; r < 4; r++) {
            float4 w4 = __ldg(wr + r * 4);
            ull wlo = pk(w4.x, w4.y), whi = pk(w4.z, w4.w);
            float va = (r == 0) ? xa.x : (r == 1) ? xa.y : (r == 2) ? xa.z : xa.w;
            float vb = (r == 0) ? xb.x : (r == 1) ? xb.y : (r == 2) ? xb.z : xb.w;
            ull da = pk(va, va), db = pk(vb, vb);
            FMAX2(acc[0][0], da, wlo); FMAX2(acc[0][1], da, whi);
            FMAX2(acc[1][0], db, wlo); FMAX2(acc[1][1], db, whi);
        }
    }
}

__global__ __launch_bounds__(512, 2)
void memetic_fused_kernel(
    const float* __restrict__ h, const float* __restrict__ u, const float* __restrict__ z,
    const float* __restrict__ qd_down, const float* __restrict__ qd_up,
    const float* __restrict__ kd_down, const float* __restrict__ kd_up,
    const float* __restrict__ vd_down, const float* __restrict__ vd_up,
    const float* __restrict__ od_down, const float* __restrict__ od_up,
    const float* __restrict__ ug_w, const float* __restrict__ ug_b,
    const float* __restrict__ cand_w, const float* __restrict__ cand_b,
    const float* __restrict__ eta_logit,
    float* __restrict__ out_c, float* __restrict__ out_z,
    float* __restrict__ out_attn, float* __restrict__ out_q,
    float* __restrict__ out_k, float* __restrict__ out_v)
{
    extern __shared__ float sm[];
    float* sh_h = sm + OFF_H;
    float* sh_z = sm + OFF_Z;
    float* sh_c = sm + OFF_C;
    float* sq   = sm + OFF_Q;
    float* sk   = sm + OFF_K;
    float* sv   = sm + OFF_V;
    float* sat  = sm + OFF_AT;
    float* sclat = sq;           // alias: q dead after C1
    float* sred  = sk;           // alias: k dead after C2 (needs 3072 fl <= 4352)
    float* sgc   = sat;          // alias: at dead after C2

    const int bp    = blockIdx.x >> 1;       // batch
    const int tbase = (blockIdx.x & 1) << 5; // token base (0 or 32)
    const int tid  = threadIdx.x;
    const int wid  = tid >> 5;
    const int lane = tid & 31;
    const float NEG_INF = __int_as_float(0xff800000);
    const float* hb = h + (size_t)bp * (NN * 256);

    // ---------------- Phase A: stage own h rows + z ----------------
    {
        const float4* hb4 = reinterpret_cast<const float4*>(hb);
        #pragma unroll
        for (int c = 0; c < 2; c++) {
            int row = (wid << 1) + c;                 // local 0..31
            #pragma unroll
            for (int it = 0; it < 2; it++) {
                int c4 = lane + (it << 5);
                float4 v4 = hb4[(tbase + row) * 64 + c4];
                *reinterpret_cast<float4*>(sh_h + row * 260 + (c4 << 2)) = v4;
            }
        }
        const float* zb = z + (size_t)bp * (NN * 16) + tbase * 16;
        for (int i = tid; i < 32 * 16; i += 512)
            sh_z[(i >> 4) * 20 + (i & 15)] = zb[i];
    }
    __syncthreads();

    // ---------------- Phase B (warp-specialized): q (warps 0-7), k+v (warps 8-15) ----------------
    if (wid < 8) {
        // q for own 32 tokens, 4 per warp; qd_down hoisted once per warp
        const float4* qdd4 = reinterpret_cast<const float4*>(qd_down);
        float4 qw[8];
        #pragma unroll
        for (int it = 0; it < 8; it++) qw[it] = __ldg(qdd4 + lane + it * 32);
        float4 qwz = make_float4(0.f, 0.f, 0.f, 0.f);
        if (lane < 16) qwz = __ldg(qdd4 + 256 + lane);
        #pragma unroll
        for (int c0 = 0; c0 < 4; c0++) {
            const int t = (wid << 2) + c0;            // local 0..31
            float q0, q1, q2, q3;
            {
                float xz = (lane < 16) ? sh_z[t * 20 + lane] : 0.f;
                q0 = xz * qwz.x; q1 = xz * qwz.y; q2 = xz * qwz.z; q3 = xz * qwz.w;
            }
            #pragma unroll
            for (int it = 0; it < 8; it++) {
                float x = sh_h[t * 260 + lane + it * 32];
                q0 += x * qw[it].x; q1 += x * qw[it].y; q2 += x * qw[it].z; q3 += x * qw[it].w;
            }
            q0 = wsum32(q0); q1 = wsum32(q1); q2 = wsum32(q2); q3 = wsum32(q3);
            const size_t tok = (size_t)(bp * NN + tbase + t);
            #pragma unroll
            for (int s = 0; s < 2; s++) {
                int d = lane + (s << 5);
                float qv = 0.25f * (q0 * __ldg(qd_up + d)       + q1 * __ldg(qd_up + 64 + d)
                                  + q2 * __ldg(qd_up + 128 + d) + q3 * __ldg(qd_up + 192 + d));
                sq[t * 68 + d] = qv;
                out_q[tok * 64 + d] = qv;
            }
        }
    } else {
        // k,v for all 64 tokens, 8 per warp; kd/vd_down hoisted once per warp
        const float* ub = u + (size_t)bp * (NN * 128);
        const float4* kdd4 = reinterpret_cast<const float4*>(kd_down);
        const float4* vdd4 = reinterpret_cast<const float4*>(vd_down);
        float4 kw4[4], vw4[4];
        #pragma unroll
        for (int it = 0; it < 4; it++) {
            kw4[it] = __ldg(kdd4 + lane + it * 32);
            vw4[it] = __ldg(vdd4 + lane + it * 32);
        }
        const int w2 = wid - 8;
        #pragma unroll
        for (int c0 = 0; c0 < 8; c0++) {
            const int t = (w2 << 3) + c0;             // global token 0..63
            float k0 = 0.f, k1 = 0.f, k2 = 0.f, k3 = 0.f;
            float v0 = 0.f, v1 = 0.f, v2 = 0.f, v3 = 0.f;
            #pragma unroll
            for (int it = 0; it < 4; it++) {
                float x = __ldg(ub + t * 128 + lane + it * 32);
                k0 += x * kw4[it].x; k1 += x * kw4[it].y; k2 += x * kw4[it].z; k3 += x * kw4[it].w;
                v0 += x * vw4[it].x; v1 += x * vw4[it].y; v2 += x * vw4[it].z; v3 += x * vw4[it].w;
            }
            k0 = wsum32(k0); k1 = wsum32(k1); k2 = wsum32(k2); k3 = wsum32(k3);
            v0 = wsum32(v0); v1 = wsum32(v1); v2 = wsum32(v2); v3 = wsum32(v3);
            const bool own = (t >= tbase) && (t < tbase + 32);
            const size_t tok = (size_t)(bp * NN + t);
            #pragma unroll
            for (int s = 0; s < 2; s++) {
                int d = lane + (s << 5);
                float kv = 0.25f * (k0 * __ldg(kd_up + d)       + k1 * __ldg(kd_up + 64 + d)
                                  + k2 * __ldg(kd_up + 128 + d) + k3 * __ldg(kd_up + 192 + d));
                float vv = 0.25f * (v0 * __ldg(vd_up + d)       + v1 * __ldg(vd_up + 64 + d)
                                  + v2 * __ldg(vd_up + 128 + d) + v3 * __ldg(vd_up + 192 + d));
                sk[t * 68 + d] = kv;
                sv[t * 68 + d] = vv;
                if (own) {
                    out_k[tok * 64 + d] = kv;
                    out_v[tok * 64 + d] = vv;
                }
            }
        }
    }
    __syncthreads();

    // ---------------- Phase C1: scores[32][64]; 4 tiles (16n x 32m), 4-way d-split ----------------
    {
        const int tile = wid >> 2, ks = wid & 3;
        const int n0 = ((tile >> 1) << 4) + (lane & 3);   // + 4a
        const int mb = ((tile & 1) << 5) + (lane >> 2);   // + 8bb
        ull acc[4][4];
        #pragma unroll
        for (int a = 0; a < 4; a++)
            #pragma unroll
            for (int bb = 0; bb < 4; bb++) acc[a][bb] = 0ull;
        #pragma unroll
        for (int s = 0; s < 4; s++) {
            const int dd = (ks << 4) + (s << 2);
            ull klo[4], khi[4];
            #pragma unroll
            for (int bb = 0; bb < 4; bb++) {
                ulonglong2 kp = *reinterpret_cast<const ulonglong2*>(sk + (mb + 8 * bb) * 68 + dd);
                klo[bb] = kp.x; khi[bb] = kp.y;
            }
            #pragma unroll
            for (int a = 0; a < 4; a++) {
                ulonglong2 qp = *reinterpret_cast<const ulonglong2*>(sq + (n0 + 4 * a) * 68 + dd);
                #pragma unroll
                for (int bb = 0; bb < 4; bb++) {
                    FMAX2(acc[a][bb], qp.x, klo[bb]);
                    FMAX2(acc[a][bb], qp.y, khi[bb]);
                }
            }
        }
        float sc[4][4];
        #pragma unroll
        for (int a = 0; a < 4; a++)
            #pragma unroll
            for (int bb = 0; bb < 4; bb++) {
                float lo, hi; upk(acc[a][bb], lo, hi); sc[a][bb] = lo + hi;
            }
        // sequential in-place reduction: ks 3 -> 2 -> 1 -> 0
        if (ks == 3) {
            #pragma unroll
            for (int a = 0; a < 4; a++)
                #pragma unroll
                for (int bb = 0; bb < 4; bb++)
                    sat[(n0 + 4 * a) * 68 + mb + 8 * bb] = sc[a][bb];
        }
        __syncthreads();
        if (ks == 2) {
            #pragma unroll
            for (int a = 0; a < 4; a++)
                #pragma unroll
                for (int bb = 0; bb < 4; bb++)
                    sat[(n0 + 4 * a) * 68 + mb + 8 * bb] += sc[a][bb];
        }
        __syncthreads();
        if (ks == 1) {
            #pragma unroll
            for (int a = 0; a < 4; a++)
                #pragma unroll
                for (int bb = 0; bb < 4; bb++)
                    sat[(n0 + 4 * a) * 68 + mb + 8 * bb] += sc[a][bb];
        }
        __syncthreads();
        if (ks == 0) {
            #pragma unroll
            for (int a = 0; a < 4; a++) {
                const int n = n0 + 4 * a;
                #pragma unroll
                for (int bb = 0; bb < 4; bb++) {
                    const int m = mb + 8 * bb;
                    float r = (sc[a][bb] + sat[n * 68 + m]) * 0.125f;
                    if (tbase + n == m) r = NEG_INF;
                    sat[n * 68 + m] = r;
                }
            }
        }
        __syncthreads();
    }

    // ---------------- Phase C1b: softmax (2 rows per warp) ----------------
    {
        #pragma unroll
        for (int rr = 0; rr < 2; rr++) {
            int n = (wid << 1) + rr;
            float s0 = sat[n * 68 + lane];
            float s1 = sat[n * 68 + lane + 32];
            float mx = wmax32(fmaxf(s0, s1));
            float e0 = __expf(s0 - mx), e1 = __expf(s1 - mx);
            float inv = 1.f / wsum32(e0 + e1);
            float a0 = e0 * inv, a1 = e1 * inv;
            sat[n * 68 + lane]      = a0;
            sat[n * 68 + lane + 32] = a1;
            size_t tk = (size_t)(bp * NN + tbase + n) * 64;
            out_attn[tk + lane]      = a0;
            out_attn[tk + lane + 32] = a1;
        }
    }
    __syncthreads();

    // ---------------- Phase C2: clat[32][64]; 4 tiles (16n x 32d), 4-way m-split ----------------
    {
        const int tile = wid >> 2, ks = wid & 3;
        const int n0 = ((tile >> 1) << 4) + (lane & 3);
        const int d0 = ((tile & 1) << 5) + ((lane >> 2) << 2);
        ull acc[4][2];
        #pragma unroll
        for (int a = 0; a < 4; a++) { acc[a][0] = 0ull; acc[a][1] = 0ull; }
        #pragma unroll
        for (int s = 0; s < 4; s++) {
            const int mm = (ks << 4) + (s << 2);
            ull vlo[4], vhi[4];
            #pragma unroll
            for (int t = 0; t < 4; t++) {
                ulonglong2 vp = *reinterpret_cast<const ulonglong2*>(sv + (mm + t) * 68 + d0);
                vlo[t] = vp.x; vhi[t] = vp.y;
            }
            #pragma unroll
            for (int a = 0; a < 4; a++) {
                float4 a4 = *reinterpret_cast<const float4*>(sat + (n0 + 4 * a) * 68 + mm);
                ull a0 = pk(a4.x, a4.x), a1 = pk(a4.y, a4.y);
                ull a2 = pk(a4.z, a4.z), a3 = pk(a4.w, a4.w);
                FMAX2(acc[a][0], a0, vlo[0]); FMAX2(acc[a][1], a0, vhi[0]);
                FMAX2(acc[a][0], a1, vlo[1]); FMAX2(acc[a][1], a1, vhi[1]);
                FMAX2(acc[a][0], a2, vlo[2]); FMAX2(acc[a][1], a2, vhi[2]);
                FMAX2(acc[a][0], a3, vlo[3]); FMAX2(acc[a][1], a3, vhi[3]);
            }
        }
        // sequential in-place reduction into sclat (float4)
        if (ks == 3) {
            #pragma unroll
            for (int a = 0; a < 4; a++) {
                float x0, x1, x2, x3;
                upk(acc[a][0], x0, x1); upk(acc[a][1], x2, x3);
                *reinterpret_cast<float4*>(sclat + (n0 + 4 * a) * 68 + d0) =
                    make_float4(x0, x1, x2, x3);
            }
        }
        __syncthreads();
        #pragma unroll
        for (int stage = 2; stage >= 0; stage--) {
            if (ks == stage) {
                #pragma unroll
                for (int a = 0; a < 4; a++) {
                    float4 p = *reinterpret_cast<const float4*>(sclat + (n0 + 4 * a) * 68 + d0);
                    float x0, x1, x2, x3;
                    upk(acc[a][0], x0, x1); upk(acc[a][1], x2, x3);
                    *reinterpret_cast<float4*>(sclat + (n0 + 4 * a) * 68 + d0) =
                        make_float4(x0 + p.x, x1 + p.y, x2 + p.z, x3 + p.w);
                }
            }
            __syncthreads();
        }
    }

    // ---------------- Phase C3: rank-4 output projection (2 tokens per warp) ----------------
    {
        const float4* odd4 = reinterpret_cast<const float4*>(od_down);
        float4 o0 = __ldg(odd4 + lane);
        float4 o1 = __ldg(odd4 + lane + 32);
        #pragma unroll
        for (int c0 = 0; c0 < 2; c0++) {
            int t = (wid << 1) + c0;
            float ca = sclat[t * 68 + lane];
            float cb = sclat[t * 68 + lane + 32];
            float r0 = wsum32(ca * o0.x + cb * o1.x);
            float r1 = wsum32(ca * o0.y + cb * o1.y);
            float r2 = wsum32(ca * o0.z + cb * o1.z);
            float r3 = wsum32(ca * o0.w + cb * o1.w);
            size_t tk = (size_t)(bp * NN + tbase + t) * 128;
            #pragma unroll
            for (int s = 0; s < 4; s++) {
                int j = lane + (s << 5);
                float cv = 0.25f * (r0 * __ldg(od_up + j)       + r1 * __ldg(od_up + 128 + j)
                                  + r2 * __ldg(od_up + 256 + j) + r3 * __ldg(od_up + 384 + j));
                sh_c[t * 132 + j] = cv;
                out_c[tk + j] = cv;
            }
        }
    }
    __syncthreads();

    // ---------------- Phase D: gate/cand matmuls; x in smem, w via LDG ----------------
    {
        const int ip   = wid & 3;
        const int tile = wid >> 2;
        const int th   = tile >> 1;
        const int j0   = (tile & 1) * 16 + (lane >> 3) * 4;   // 0..31
        const int t0   = th * 16 + (lane & 7);                // + 8c
        const float* wsel = (j0 < 16) ? ug_w : cand_w;
        const int j4 = (j0 & 15) >> 2;
        ull acc[2][2];
        acc[0][0] = 0ull; acc[0][1] = 0ull; acc[1][0] = 0ull; acc[1][1] = 0ull;
        const float* xh = sh_h + t0 * 260;
        const float* xz = sh_z + t0 * 20;
        const float* xc = sh_c + t0 * 132;
        if (ip == 0) {
            d_accum(xz, 20, wsel, 0, 4, j4, acc);
            d_accum(xh, 260, wsel, 16, 21, j4, acc);
        } else if (ip == 1) {
            d_accum(xh + 84, 260, wsel, 100, 25, j4, acc);
        } else if (ip == 2) {
            d_accum(xh + 184, 260, wsel, 200, 18, j4, acc);
            d_accum(xc, 132, wsel, 272, 7, j4, acc);
        } else {
            d_accum(xc + 28, 132, wsel, 300, 25, j4, acc);
        }
        float f[2][4];
        #pragma unroll
        for (int c = 0; c < 2; c++) {
            upk(acc[c][0], f[c][0], f[c][1]);
            upk(acc[c][1], f[c][2], f[c][3]);
        }
        __syncthreads();   // k fully dead -> sred safe
        if (ip != 0) {
            float* dst = sred + (tile * 3 + (ip - 1)) * 256;
            #pragma unroll
            for (int c = 0; c < 2; c++)
                #pragma unroll
                for (int d = 0; d < 4; d++)
                    dst[(c * 4 + d) * 32 + lane] = f[c][d];
        }
        __syncthreads();
        if (ip == 0) {
            #pragma unroll
            for (int s = 0; s < 3; s++) {
                const float* src = sred + (tile * 3 + s) * 256;
                #pragma unroll
                for (int c = 0; c < 2; c++)
                    #pragma unroll
                    for (int d = 0; d < 4; d++)
                        f[c][d] += src[(c * 4 + d) * 32 + lane];
            }
            #pragma unroll
            for (int d = 0; d < 4; d++) {
                int j = j0 + d;
                float bias = (j < 16) ? __ldg(ug_b + j) : __ldg(cand_b + j - 16);
                #pragma unroll
                for (int c = 0; c < 2; c++)
                    sgc[(t0 + 8 * c) * 33 + j] = f[c][d] + bias;
            }
        }
    }
    __syncthreads();

    // ---------------- Phase E: gated update + layernorm (2 tokens per warp) ----------------
    {
        const float eta = 1.f / (1.f + __expf(-__ldg(eta_logit)));
        const int s = lane >> 4;
        const int j = lane & 15;
        int t = (wid << 1) + s;
        float gp = sgc[t * 33 + j];
        float cp = sgc[t * 33 + 16 + j];
        float eg = eta * (1.f / (1.f + __expf(-gp)));
        float val = (1.f - eg) * sh_z[t * 20 + j] + eg * tanhf(cp);
        float sum = val;
        #pragma unroll
        for (int msk = 8; msk > 0; msk >>= 1)
            sum += __shfl_xor_sync(0xffffffffu, sum, msk, 16);
        float mu = sum * (1.f / 16.f);
        float dv = val - mu;
        float vs = dv * dv;
        #pragma unroll
        for (int msk = 8; msk > 0; msk >>= 1)
            vs += __shfl_xor_sync(0xffffffffu, vs, msk, 16);
        float var = vs * (1.f / 16.f);
        out_z[(size_t)(bp * NN + tbase + t) * 16 + j] = dv * rsqrtf(var + 1e-5f);
    }
}

extern "C" void kernel_launch(void* const* d_in, const int* in_sizes, int n_in,
                              void* d_out, int out_size) {
    const float* h        = (const float*)d_in[0];
    const float* u        = (const float*)d_in[1];
    const float* z        = (const float*)d_in[2];
    const float* qd_down  = (const float*)d_in[3];
    const float* qd_up    = (const float*)d_in[4];
    const float* kd_down  = (const float*)d_in[5];
    const float* kd_up    = (const float*)d_in[6];
    const float* vd_down  = (const float*)d_in[7];
    const float* vd_up    = (const float*)d_in[8];
    const float* od_down  = (const float*)d_in[9];
    const float* od_up    = (const float*)d_in[10];
    const float* ug_w     = (const float*)d_in[11];
    const float* ug_b     = (const float*)d_in[12];
    const float* cand_w   = (const float*)d_in[13];
    const float* cand_b   = (const float*)d_in[14];
    const float* eta_logit= (const float*)d_in[15];

    float* o = (float*)d_out;
    float* out_c    = o;                        // 4096*64*128
    float* out_z    = o + (size_t)33554432;     // 4096*64*16
    float* out_attn = o + (size_t)37748736;     // 4096*64*64
    float* out_q    = o + (size_t)54525952;
    float* out_k    = o + (size_t)71303168;
    float* out_v    = o + (size_t)88080384;

    const int smem_bytes = SMEM_FLOATS * sizeof(float);  // 104960
    cudaFuncSetAttribute(memetic_fused_kernel,
                         cudaFuncAttributeMaxDynamicSharedMemorySize, smem_bytes);

    memetic_fused_kernel<<<BB * 2, 512, smem_bytes>>>(
        h, u, z, qd_down, qd_up, kd_down, kd_up, vd_down, vd_up,
        od_down, od_up, ug_w, ug_b, cand_w, cand_b, eta_logit,
        out_c, out_z, out_attn, out_q, out_k, out_v);
}

// round 11
// speedup vs baseline: 1.3394x; 1.3394x over previous
#include <cuda_runtime.h>
#include <math.h>

#define BB 4096
#define NN 64

// Per-CTA smem (floats), 108,544 bytes -> 2 CTAs/SM:
//  sh_z [64][20]  = 1280
//  sh_c [64][132] = 8448
//  sq   [64][68]  = 4352  q -> clat (C2) -> sred tiles 0,1 (D)
//  sk   [64][68]  = 4352  k -> h staging buffer (D)
//  sv   [64][68]  = 4352  v -> sred tiles 2,3 (D)
//  sat  [64][68]  = 4352  scores/attn -> gate/cand (D/E)
#define OFF_Z   0
#define OFF_C   1280
#define OFF_Q   9728
#define OFF_K   14080
#define OFF_V   18432
#define OFF_AT  22784
#define SMEM_FLOATS 27136

typedef unsigned long long ull;

__device__ __forceinline__ ull pk(float a, float b) {
    ull r; asm("mov.b64 %0, {%1, %2};" : "=l"(r) : "f"(a), "f"(b)); return r;
}
__device__ __forceinline__ void upk(ull v, float& a, float& b) {
    asm("mov.b64 {%0, %1}, %2;" : "=f"(a), "=f"(b) : "l"(v));
}
#define FMAX2(acc, a, b) asm("fma.rn.f32x2 %0, %1, %2, %0;" : "+l"(acc) : "l"(a), "l"(b))

__device__ __forceinline__ float wsum32(float v) {
    #pragma unroll
    for (int m = 16; m > 0; m >>= 1) v += __shfl_xor_sync(0xffffffffu, v, m);
    return v;
}
__device__ __forceinline__ float wmax32(float v) {
    #pragma unroll
    for (int m = 16; m > 0; m >>= 1) v = fmaxf(v, __shfl_xor_sync(0xffffffffu, v, m));
    return v;
}

// Phase-D inner: 4 tokens (delta-8 rows, smem x) x 16 outputs over n4*4 k-rows; w via LDG.
__device__ __forceinline__ void d_accum(const float* __restrict__ x0, int xs,
                                        const float* __restrict__ wsel, int ibase,
                                        int n4, int j4, ull acc[4][2]) {
    for (int s = 0; s < n4; s++) {
        const int il = s << 2;
        float4 x4[4];
        #pragma unroll
        for (int c = 0; c < 4; c++)
            x4[c] = *reinterpret_cast<const float4*>(x0 + c * 8 * xs + il);
        const float4* wr = reinterpret_cast<const float4*>(wsel + (ibase + il) * 16) + j4;
        #pragma unroll
        for (int r = 0; r < 4; r++) {
            float4 w4 = __ldg(wr + r * 4);
            ull wlo = pk(w4.x, w4.y), whi = pk(w4.z, w4.w);
            #pragma unroll
            for (int c = 0; c < 4; c++) {
                float xv = (r == 0) ? x4[c].x : (r == 1) ? x4[c].y : (r == 2) ? x4[c].z : x4[c].w;
                ull xd = pk(xv, xv);
                FMAX2(acc[c][0], xd, wlo);
                FMAX2(acc[c][1], xd, whi);
            }
        }
    }
}

__global__ __launch_bounds__(512, 2)
void memetic_fused_kernel(
    const float* __restrict__ h, const float* __restrict__ u, const float* __restrict__ z,
    const float* __restrict__ qd_down, const float* __restrict__ qd_up,
    const float* __restrict__ kd_down, const float* __restrict__ kd_up,
    const float* __restrict__ vd_down, const float* __restrict__ vd_up,
    const float* __restrict__ od_down, const float* __restrict__ od_up,
    const float* __restrict__ ug_w, const float* __restrict__ ug_b,
    const float* __restrict__ cand_w, const float* __restrict__ cand_b,
    const float* __restrict__ eta_logit,
    float* __restrict__ out_c, float* __restrict__ out_z,
    float* __restrict__ out_attn, float* __restrict__ out_q,
    float* __restrict__ out_k, float* __restrict__ out_v)
{
    extern __shared__ float sm[];
    float* sh_z = sm + OFF_Z;
    float* sh_c = sm + OFF_C;
    float* sq   = sm + OFF_Q;
    float* sk   = sm + OFF_K;
    float* sv   = sm + OFF_V;
    float* sat  = sm + OFF_AT;
    float* sclat = sq;           // alias: q dead after C1
    float* hst   = sk;           // alias: k dead after C1 -> h staging in D
    float* sgc   = sat;          // alias: at dead after C2

    const int b    = blockIdx.x;
    const int tid  = threadIdx.x;
    const int wid  = tid >> 5;
    const int lane = tid & 31;
    const float NEG_INF = __int_as_float(0xff800000);
    const float* hb = h + (size_t)b * (NN * 256);
    const float4* hb4 = reinterpret_cast<const float4*>(hb);

    // ---------------- Phase A: stage z ----------------
    {
        const float* zb = z + (size_t)b * (NN * 16);
        for (int i = tid; i < NN * 16; i += 512)
            sh_z[(i >> 4) * 20 + (i & 15)] = zb[i];
    }
    __syncthreads();

    // ---------------- Phase B: q, k, v (warp per token, 4 tokens/warp) ----------------
    {
        const float* ub = u + (size_t)b * (NN * 128);
        const float4* qdd4 = reinterpret_cast<const float4*>(qd_down);
        const float4* kdd4 = reinterpret_cast<const float4*>(kd_down);
        const float4* vdd4 = reinterpret_cast<const float4*>(vd_down);
        for (int c0 = 0; c0 < 4; c0++) {
            const int t = (wid << 2) + c0;
            const float* hrow = hb + t * 256;
            float q0 = 0.f, q1 = 0.f, q2 = 0.f, q3 = 0.f;
            #pragma unroll
            for (int it = 0; it < 8; it++) {
                int i = lane + it * 32;
                float x = __ldg(hrow + i);
                float4 wv = __ldg(qdd4 + i);
                q0 += x * wv.x; q1 += x * wv.y; q2 += x * wv.z; q3 += x * wv.w;
            }
            if (lane < 16) {
                float x = sh_z[t * 20 + lane];
                float4 wv = __ldg(qdd4 + 256 + lane);
                q0 += x * wv.x; q1 += x * wv.y; q2 += x * wv.z; q3 += x * wv.w;
            }
            q0 = wsum32(q0); q1 = wsum32(q1); q2 = wsum32(q2); q3 = wsum32(q3);
            float k0 = 0.f, k1 = 0.f, k2 = 0.f, k3 = 0.f;
            float v0 = 0.f, v1 = 0.f, v2 = 0.f, v3 = 0.f;
            #pragma unroll
            for (int it = 0; it < 4; it++) {
                int i = lane + it * 32;
                float x = __ldg(ub + t * 128 + i);
                float4 kw = __ldg(kdd4 + i);
                float4 vw = __ldg(vdd4 + i);
                k0 += x * kw.x; k1 += x * kw.y; k2 += x * kw.z; k3 += x * kw.w;
                v0 += x * vw.x; v1 += x * vw.y; v2 += x * vw.z; v3 += x * vw.w;
            }
            k0 = wsum32(k0); k1 = wsum32(k1); k2 = wsum32(k2); k3 = wsum32(k3);
            v0 = wsum32(v0); v1 = wsum32(v1); v2 = wsum32(v2); v3 = wsum32(v3);
            const size_t tok = (size_t)(b * NN + t);
            #pragma unroll
            for (int s = 0; s < 2; s++) {
                int d = lane + (s << 5);
                float qv = 0.25f * (q0 * __ldg(qd_up + d)       + q1 * __ldg(qd_up + 64 + d)
                                  + q2 * __ldg(qd_up + 128 + d) + q3 * __ldg(qd_up + 192 + d));
                float kv = 0.25f * (k0 * __ldg(kd_up + d)       + k1 * __ldg(kd_up + 64 + d)
                                  + k2 * __ldg(kd_up + 128 + d) + k3 * __ldg(kd_up + 192 + d));
                float vv = 0.25f * (v0 * __ldg(vd_up + d)       + v1 * __ldg(vd_up + 64 + d)
                                  + v2 * __ldg(vd_up + 128 + d) + v3 * __ldg(vd_up + 192 + d));
                sq[t * 68 + d] = qv;
                sk[t * 68 + d] = kv;
                sv[t * 68 + d] = vv;
                out_q[tok * 64 + d] = qv;
                out_k[tok * 64 + d] = kv;
                out_v[tok * 64 + d] = vv;
            }
        }
    }
    __syncthreads();

    // ---------------- Phase C1: QK scores; 16n x 32m tiles, thread 4x4, 2-warp d-split ----------------
    {
        const int tile = wid >> 1, ks = wid & 1;
        const int nb = ((tile >> 1) << 4) + (lane & 3);
        const int mb = ((tile & 1) << 5) + (lane >> 2);
        ull acc[4][4];
        #pragma unroll
        for (int a = 0; a < 4; a++)
            #pragma unroll
            for (int bb = 0; bb < 4; bb++) acc[a][bb] = 0ull;
        #pragma unroll
        for (int s = 0; s < 8; s++) {
            const int dd = (ks << 5) + (s << 2);
            ull klo[4], khi[4];
            #pragma unroll
            for (int bb = 0; bb < 4; bb++) {
                ulonglong2 kp = *reinterpret_cast<const ulonglong2*>(sk + (mb + 8 * bb) * 68 + dd);
                klo[bb] = kp.x; khi[bb] = kp.y;
            }
            #pragma unroll
            for (int a = 0; a < 4; a++) {
                ulonglong2 qp = *reinterpret_cast<const ulonglong2*>(sq + (nb + 4 * a) * 68 + dd);
                #pragma unroll
                for (int bb = 0; bb < 4; bb++) {
                    FMAX2(acc[a][bb], qp.x, klo[bb]);
                    FMAX2(acc[a][bb], qp.y, khi[bb]);
                }
            }
        }
        float sc[4][4];
        #pragma unroll
        for (int a = 0; a < 4; a++)
            #pragma unroll
            for (int bb = 0; bb < 4; bb++) {
                float lo, hi; upk(acc[a][bb], lo, hi); sc[a][bb] = lo + hi;
            }
        if (ks == 1) {
            #pragma unroll
            for (int a = 0; a < 4; a++)
                #pragma unroll
                for (int bb = 0; bb < 4; bb++)
                    sat[(nb + 4 * a) * 68 + mb + 8 * bb] = sc[a][bb];
        }
        __syncthreads();
        if (ks == 0) {
            #pragma unroll
            for (int a = 0; a < 4; a++) {
                const int n = nb + 4 * a;
                #pragma unroll
                for (int bb = 0; bb < 4; bb++) {
                    const int m = mb + 8 * bb;
                    float r = (sc[a][bb] + sat[n * 68 + m]) * 0.125f;
                    if (n == m) r = NEG_INF;
                    sat[n * 68 + m] = r;
                }
            }
        }
        __syncthreads();
    }

    // ---------------- Phase C1b: softmax (warp per 4 rows) ----------------
    {
        #pragma unroll
        for (int rr = 0; rr < 4; rr++) {
            int n = (wid << 2) + rr;
            float s0 = sat[n * 68 + lane];
            float s1 = sat[n * 68 + lane + 32];
            float mx = wmax32(fmaxf(s0, s1));
            float e0 = __expf(s0 - mx), e1 = __expf(s1 - mx);
            float inv = 1.f / wsum32(e0 + e1);
            float a0 = e0 * inv, a1 = e1 * inv;
            sat[n * 68 + lane]      = a0;
            sat[n * 68 + lane + 32] = a1;
            size_t tk = (size_t)(b * NN + n) * 64;
            out_attn[tk + lane]      = a0;
            out_attn[tk + lane + 32] = a1;
        }
    }
    __syncthreads();

    // ---------------- Phase C2: clat = attn @ v; same tiling, 2-warp m-split ----------------
    {
        const int tile = wid >> 1, ks = wid & 1;
        const int nb = ((tile >> 1) << 4) + (lane & 3);
        const int d0 = ((tile & 1) << 5) + ((lane >> 2) << 2);
        ull acc[4][2];
        #pragma unroll
        for (int a = 0; a < 4; a++) { acc[a][0] = 0ull; acc[a][1] = 0ull; }
        #pragma unroll
        for (int s = 0; s < 8; s++) {
            const int mm = (ks << 5) + (s << 2);
            ull vlo[4], vhi[4];
            #pragma unroll
            for (int t = 0; t < 4; t++) {
                ulonglong2 vp = *reinterpret_cast<const ulonglong2*>(sv + (mm + t) * 68 + d0);
                vlo[t] = vp.x; vhi[t] = vp.y;
            }
            #pragma unroll
            for (int a = 0; a < 4; a++) {
                float4 a4 = *reinterpret_cast<const float4*>(sat + (nb + 4 * a) * 68 + mm);
                ull a0 = pk(a4.x, a4.x), a1 = pk(a4.y, a4.y);
                ull a2 = pk(a4.z, a4.z), a3 = pk(a4.w, a4.w);
                FMAX2(acc[a][0], a0, vlo[0]); FMAX2(acc[a][1], a0, vhi[0]);
                FMAX2(acc[a][0], a1, vlo[1]); FMAX2(acc[a][1], a1, vhi[1]);
                FMAX2(acc[a][0], a2, vlo[2]); FMAX2(acc[a][1], a2, vhi[2]);
                FMAX2(acc[a][0], a3, vlo[3]); FMAX2(acc[a][1], a3, vhi[3]);
            }
        }
        if (ks == 1) {
            #pragma unroll
            for (int a = 0; a < 4; a++) {
                float x0, x1, x2, x3;
                upk(acc[a][0], x0, x1); upk(acc[a][1], x2, x3);
                *reinterpret_cast<float4*>(sclat + (nb + 4 * a) * 68 + d0) =
                    make_float4(x0, x1, x2, x3);
            }
        }
        __syncthreads();
        if (ks == 0) {
            #pragma unroll
            for (int a = 0; a < 4; a++) {
                float4 p = *reinterpret_cast<const float4*>(sclat + (nb + 4 * a) * 68 + d0);
                float x0, x1, x2, x3;
                upk(acc[a][0], x0, x1); upk(acc[a][1], x2, x3);
                *reinterpret_cast<float4*>(sclat + (nb + 4 * a) * 68 + d0) =
                    make_float4(x0 + p.x, x1 + p.y, x2 + p.z, x3 + p.w);
            }
        }
        __syncthreads();
    }

    // ---------------- Phase C3: rank-4 output projection (warp per token) ----------------
    {
        const float4* odd4 = reinterpret_cast<const float4*>(od_down);
        float4 o0 = __ldg(odd4 + lane);
        float4 o1 = __ldg(odd4 + lane + 32);
        for (int c0 = 0; c0 < 4; c0++) {
            int t = (wid << 2) + c0;
            float ca = sclat[t * 68 + lane];
            float cb = sclat[t * 68 + lane + 32];
            float r0 = wsum32(ca * o0.x + cb * o1.x);
            float r1 = wsum32(ca * o0.y + cb * o1.y);
            float r2 = wsum32(ca * o0.z + cb * o1.z);
            float r3 = wsum32(ca * o0.w + cb * o1.w);
            size_t tk = (size_t)(b * NN + t) * 128;
            #pragma unroll
            for (int s = 0; s < 4; s++) {
                int j = lane + (s << 5);
                float cv = 0.25f * (r0 * __ldg(od_up + j)       + r1 * __ldg(od_up + 128 + j)
                                  + r2 * __ldg(od_up + 256 + j) + r3 * __ldg(od_up + 384 + j));
                sh_c[t * 132 + j] = cv;
                out_c[tk + j] = cv;
            }
        }
    }
    __syncthreads();

    // ---------------- Phase D: gate/cand matmuls; h streamed via smem chunks ----------------
    {
        const int ip   = wid & 3;
        const int tile = wid >> 2;
        const int th   = tile >> 1;
        const int j0   = (tile & 1) * 16 + (lane >> 3) * 4;   // 0..31
        const int t0   = th * 32 + (lane & 7);                // + 8c -> 4 tokens
        const float* wsel = (j0 < 16) ? ug_w : cand_w;
        const int j4 = (j0 & 15) >> 2;
        ull acc[4][2];
        #pragma unroll
        for (int c = 0; c < 4; c++) { acc[c][0] = 0ull; acc[c][1] = 0ull; }

        // h part: 4 staged chunks of 64 cols through hst (= dead sk)
        const int r2 = lane >> 4, c4 = lane & 15;
        #pragma unroll
        for (int ch = 0; ch < 4; ch++) {
            #pragma unroll
            for (int rr = 0; rr < 2; rr++) {
                int row = (wid << 2) + (rr << 1) + r2;
                float4 v4 = __ldg(hb4 + row * 64 + (ch << 4) + c4);
                *reinterpret_cast<float4*>(hst + row * 68 + (c4 << 2)) = v4;
            }
            __syncthreads();
            d_accum(hst + t0 * 68 + ip * 16, 68, wsel, 16 + (ch << 6) + ip * 16, 4, j4, acc);
            __syncthreads();
        }
        // z part (i 0..15) and c part (i 272..399), split 4 ways by ip
        d_accum(sh_z + t0 * 20 + ip * 4, 20, wsel, ip * 4, 1, j4, acc);
        d_accum(sh_c + t0 * 132 + ip * 32, 132, wsel, 272 + ip * 32, 8, j4, acc);

        float f[4][4];
        #pragma unroll
        for (int c = 0; c < 4; c++) {
            upk(acc[c][0], f[c][0], f[c][1]);
            upk(acc[c][1], f[c][2], f[c][3]);
        }
        // reduction: sred tiles 0,1 in sq (dead), tiles 2,3 in sv (dead)
        float* srb = ((tile < 2) ? sq : sv) + ((tile & 1) * 3) * 512;
        if (ip != 0) {
            float* dst = srb + (ip - 1) * 512;
            #pragma unroll
            for (int c = 0; c < 4; c++)
                #pragma unroll
                for (int d = 0; d < 4; d++)
                    dst[(c * 4 + d) * 32 + lane] = f[c][d];
        }
        __syncthreads();
        if (ip == 0) {
            #pragma unroll
            for (int s = 0; s < 3; s++) {
                const float* src = srb + s * 512;
                #pragma unroll
                for (int c = 0; c < 4; c++)
                    #pragma unroll
                    for (int d = 0; d < 4; d++)
                        f[c][d] += src[(c * 4 + d) * 32 + lane];
            }
            #pragma unroll
            for (int d = 0; d < 4; d++) {
                int j = j0 + d;
                float bias = (j < 16) ? __ldg(ug_b + j) : __ldg(cand_b + j - 16);
                #pragma unroll
                for (int c = 0; c < 4; c++)
                    sgc[(t0 + 8 * c) * 33 + j] = f[c][d] + bias;
            }
        }
    }
    __syncthreads();

    // ---------------- Phase E: gated update + layernorm ----------------
    {
        const float eta = 1.f / (1.f + __expf(-__ldg(eta_logit)));
        const int s = lane >> 4;
        const int j = lane & 15;
        #pragma unroll
        for (int p = 0; p < 2; p++) {
            int t = (wid << 2) + (p << 1) + s;
            float gp = sgc[t * 33 + j];
            float cp = sgc[t * 33 + 16 + j];
            float eg = eta * (1.f / (1.f + __expf(-gp)));
            float val = (1.f - eg) * sh_z[t * 20 + j] + eg * tanhf(cp);
            float sum = val;
            #pragma unroll
            for (int msk = 8; msk > 0; msk >>= 1)
                sum += __shfl_xor_sync(0xffffffffu, sum, msk, 16);
            float mu = sum * (1.f / 16.f);
            float dv = val - mu;
            float vs = dv * dv;
            #pragma unroll
            for (int msk = 8; msk > 0; msk >>= 1)
                vs += __shfl_xor_sync(0xffffffffu, vs, msk, 16);
            float var = vs * (1.f / 16.f);
            out_z[(size_t)(b * NN + t) * 16 + j] = dv * rsqrtf(var + 1e-5f);
        }
    }
}

extern "C" void kernel_launch(void* const* d_in, const int* in_sizes, int n_in,
                              void* d_out, int out_size) {
    const float* h        = (const float*)d_in[0];
    const float* u        = (const float*)d_in[1];
    const float* z        = (const float*)d_in[2];
    const float* qd_down  = (const float*)d_in[3];
    const float* qd_up    = (const float*)d_in[4];
    const float* kd_down  = (const float*)d_in[5];
    const float* kd_up    = (const float*)d_in[6];
    const float* vd_down  = (const float*)d_in[7];
    const float* vd_up    = (const float*)d_in[8];
    const float* od_down  = (const float*)d_in[9];
    const float* od_up    = (const float*)d_in[10];
    const float* ug_w     = (const float*)d_in[11];
    const float* ug_b     = (const float*)d_in[12];
    const float* cand_w   = (const float*)d_in[13];
    const float* cand_b   = (const float*)d_in[14];
    const float* eta_logit= (const float*)d_in[15];

    float* o = (float*)d_out;
    float* out_c    = o;                        // 4096*64*128
    float* out_z    = o + (size_t)33554432;     // 4096*64*16
    float* out_attn = o + (size_t)37748736;     // 4096*64*64
    float* out_q    = o + (size_t)54525952;
    float* out_k    = o + (size_t)71303168;
    float* out_v    = o + (size_t)88080384;

    const int smem_bytes = SMEM_FLOATS * sizeof(float);  // 108544
    cudaFuncSetAttribute(memetic_fused_kernel,
                         cudaFuncAttributeMaxDynamicSharedMemorySize, smem_bytes);

    memetic_fused_kernel<<<BB, 512, smem_bytes>>>(
        h, u, z, qd_down, qd_up, kd_down, kd_up, vd_down, vd_up,
        od_down, od_up, ug_w, ug_b, cand_w, cand_b, eta_logit,
        out_c, out_z, out_attn, out_q, out_k, out_v);
}

// round 15
// speedup vs baseline: 1.4523x; 1.0843x over previous
#include <cuda_runtime.h>
#include <math.h>

#define BB 4096
#define NN 64

// Per-CTA smem (floats), 108,544 bytes -> 2 CTAs/SM:
//  sh_z [64][20]  = 1280
//  sh_c [64][132] = 8448
//  sq   [64][68]  = 4352  q -> clat (C2) -> sred tiles 0,1 (D)
//  sk   [64][68]  = 4352  k -> h staging buffer (D)
//  sv   [64][68]  = 4352  v -> sred tiles 2,3 (D)
//  sat  [64][68]  = 4352  scores/attn -> gate/cand (D/E)
#define OFF_Z   0
#define OFF_C   1280
#define OFF_Q   9728
#define OFF_K   14080
#define OFF_V   18432
#define OFF_AT  22784
#define SMEM_FLOATS 27136

typedef unsigned long long ull;

__device__ __forceinline__ ull pk(float a, float b) {
    ull r; asm("mov.b64 %0, {%1, %2};" : "=l"(r) : "f"(a), "f"(b)); return r;
}
__device__ __forceinline__ void upk(ull v, float& a, float& b) {
    asm("mov.b64 {%0, %1}, %2;" : "=f"(a), "=f"(b) : "l"(v));
}
#define FMAX2(acc, a, b) asm("fma.rn.f32x2 %0, %1, %2, %0;" : "+l"(acc) : "l"(a), "l"(b))

__device__ __forceinline__ float wsum32(float v) {
    #pragma unroll
    for (int m = 16; m > 0; m >>= 1) v += __shfl_xor_sync(0xffffffffu, v, m);
    return v;
}
__device__ __forceinline__ float wmax32(float v) {
    #pragma unroll
    for (int m = 16; m > 0; m >>= 1) v = fmaxf(v, __shfl_xor_sync(0xffffffffu, v, m));
    return v;
}

// Phase-D inner: 4 tokens (delta-8 rows, smem x) x 16 outputs over n4*4 k-rows; w via LDG.
__device__ __forceinline__ void d_accum(const float* __restrict__ x0, int xs,
                                        const float* __restrict__ wsel, int ibase,
                                        int n4, int j4, ull acc[4][2]) {
    for (int s = 0; s < n4; s++) {
        const int il = s << 2;
        float4 x4[4];
        #pragma unroll
        for (int c = 0; c < 4; c++)
            x4[c] = *reinterpret_cast<const float4*>(x0 + c * 8 * xs + il);
        const float4* wr = reinterpret_cast<const float4*>(wsel + (ibase + il) * 16) + j4;
        #pragma unroll
        for (int r = 0; r < 4; r++) {
            float4 w4 = __ldg(wr + r * 4);
            ull wlo = pk(w4.x, w4.y), whi = pk(w4.z, w4.w);
            #pragma unroll
            for (int c = 0; c < 4; c++) {
                float xv = (r == 0) ? x4[c].x : (r == 1) ? x4[c].y : (r == 2) ? x4[c].z : x4[c].w;
                ull xd = pk(xv, xv);
                FMAX2(acc[c][0], xd, wlo);
                FMAX2(acc[c][1], xd, whi);
            }
        }
    }
}

__global__ __launch_bounds__(512, 2)
void memetic_fused_kernel(
    const float* __restrict__ h, const float* __restrict__ u, const float* __restrict__ z,
    const float* __restrict__ qd_down, const float* __restrict__ qd_up,
    const float* __restrict__ kd_down, const float* __restrict__ kd_up,
    const float* __restrict__ vd_down, const float* __restrict__ vd_up,
    const float* __restrict__ od_down, const float* __restrict__ od_up,
    const float* __restrict__ ug_w, const float* __restrict__ ug_b,
    const float* __restrict__ cand_w, const float* __restrict__ cand_b,
    const float* __restrict__ eta_logit,
    float* __restrict__ out_c, float* __restrict__ out_z,
    float* __restrict__ out_attn, float* __restrict__ out_q,
    float* __restrict__ out_k, float* __restrict__ out_v)
{
    extern __shared__ float sm[];
    float* sh_z = sm + OFF_Z;
    float* sh_c = sm + OFF_C;
    float* sq   = sm + OFF_Q;
    float* sk   = sm + OFF_K;
    float* sv   = sm + OFF_V;
    float* sat  = sm + OFF_AT;
    float* sclat = sq;           // alias: q dead after C1
    float* hst   = sk;           // alias: k dead after C1 -> h staging in D
    float* sgc   = sat;          // alias: at dead after C2

    const int b    = blockIdx.x;
    const int tid  = threadIdx.x;
    const int wid  = tid >> 5;
    const int lane = tid & 31;
    const float NEG_INF = __int_as_float(0xff800000);
    const float* hb = h + (size_t)b * (NN * 256);
    const float4* hb4 = reinterpret_cast<const float4*>(hb);

    // ---------------- Phase A: stage z ----------------
    {
        const float* zb = z + (size_t)b * (NN * 16);
        for (int i = tid; i < NN * 16; i += 512)
            sh_z[(i >> 4) * 20 + (i & 15)] = zb[i];
    }
    __syncthreads();

    // ---------------- Phase B (warp-specialized): q warps 0-7, k warps 8-11, v warps 12-15 ----
    if (wid < 8) {
        const float4* qdd4 = reinterpret_cast<const float4*>(qd_down);
        float4 qw[8];
        #pragma unroll
        for (int it = 0; it < 8; it++) qw[it] = __ldg(qdd4 + lane + it * 32);
        float4 qwz = make_float4(0.f, 0.f, 0.f, 0.f);
        if (lane < 16) qwz = __ldg(qdd4 + 256 + lane);
        float qu[8];
        #pragma unroll
        for (int r = 0; r < 4; r++)
            #pragma unroll
            for (int s = 0; s < 2; s++)
                qu[r * 2 + s] = __ldg(qd_up + r * 64 + lane + (s << 5));
        for (int c0 = 0; c0 < 8; c0++) {
            const int t = (wid << 3) + c0;
            const float* hrow = hb + t * 256;
            float xz = (lane < 16) ? sh_z[t * 20 + lane] : 0.f;
            float q0 = xz * qwz.x, q1 = xz * qwz.y, q2 = xz * qwz.z, q3 = xz * qwz.w;
            #pragma unroll
            for (int it = 0; it < 8; it++) {
                float x = __ldg(hrow + lane + it * 32);
                q0 += x * qw[it].x; q1 += x * qw[it].y; q2 += x * qw[it].z; q3 += x * qw[it].w;
            }
            q0 = wsum32(q0); q1 = wsum32(q1); q2 = wsum32(q2); q3 = wsum32(q3);
            const size_t tok = (size_t)(b * NN + t);
            #pragma unroll
            for (int s = 0; s < 2; s++) {
                int d = lane + (s << 5);
                float qv = 0.25f * (q0 * qu[s] + q1 * qu[2 + s] + q2 * qu[4 + s] + q3 * qu[6 + s]);
                sq[t * 68 + d] = qv;
                out_q[tok * 64 + d] = qv;
            }
        }
    } else if (wid < 12) {
        const float* ub = u + (size_t)b * (NN * 128);
        const float4* kdd4 = reinterpret_cast<const float4*>(kd_down);
        float4 kw4[4];
        #pragma unroll
        for (int it = 0; it < 4; it++) kw4[it] = __ldg(kdd4 + lane + it * 32);
        float ku[8];
        #pragma unroll
        for (int r = 0; r < 4; r++)
            #pragma unroll
            for (int s = 0; s < 2; s++)
                ku[r * 2 + s] = __ldg(kd_up + r * 64 + lane + (s << 5));
        const int w2 = wid - 8;
        for (int c0 = 0; c0 < 16; c0++) {
            const int t = (w2 << 4) + c0;
            float k0 = 0.f, k1 = 0.f, k2 = 0.f, k3 = 0.f;
            #pragma unroll
            for (int it = 0; it < 4; it++) {
                float x = __ldg(ub + t * 128 + lane + it * 32);
                k0 += x * kw4[it].x; k1 += x * kw4[it].y; k2 += x * kw4[it].z; k3 += x * kw4[it].w;
            }
            k0 = wsum32(k0); k1 = wsum32(k1); k2 = wsum32(k2); k3 = wsum32(k3);
            const size_t tok = (size_t)(b * NN + t);
            #pragma unroll
            for (int s = 0; s < 2; s++) {
                int d = lane + (s << 5);
                float kv = 0.25f * (k0 * ku[s] + k1 * ku[2 + s] + k2 * ku[4 + s] + k3 * ku[6 + s]);
                sk[t * 68 + d] = kv;
                out_k[tok * 64 + d] = kv;
            }
        }
    } else {
        const float* ub = u + (size_t)b * (NN * 128);
        const float4* vdd4 = reinterpret_cast<const float4*>(vd_down);
        float4 vw4[4];
        #pragma unroll
        for (int it = 0; it < 4; it++) vw4[it] = __ldg(vdd4 + lane + it * 32);
        float vu[8];
        #pragma unroll
        for (int r = 0; r < 4; r++)
            #pragma unroll
            for (int s = 0; s < 2; s++)
                vu[r * 2 + s] = __ldg(vd_up + r * 64 + lane + (s << 5));
        const int w2 = wid - 12;
        for (int c0 = 0; c0 < 16; c0++) {
            const int t = (w2 << 4) + c0;
            float v0 = 0.f, v1 = 0.f, v2 = 0.f, v3 = 0.f;
            #pragma unroll
            for (int it = 0; it < 4; it++) {
                float x = __ldg(ub + t * 128 + lane + it * 32);
                v0 += x * vw4[it].x; v1 += x * vw4[it].y; v2 += x * vw4[it].z; v3 += x * vw4[it].w;
            }
            v0 = wsum32(v0); v1 = wsum32(v1); v2 = wsum32(v2); v3 = wsum32(v3);
            const size_t tok = (size_t)(b * NN + t);
            #pragma unroll
            for (int s = 0; s < 2; s++) {
                int d = lane + (s << 5);
                float vv = 0.25f * (v0 * vu[s] + v1 * vu[2 + s] + v2 * vu[4 + s] + v3 * vu[6 + s]);
                sv[t * 68 + d] = vv;
                out_v[tok * 64 + d] = vv;
            }
        }
    }
    __syncthreads();

    // ---------------- Phase C1: QK scores; 16n x 32m tiles, thread 4x4, 2-warp d-split ----------------
    {
        const int tile = wid >> 1, ks = wid & 1;
        const int nb = ((tile >> 1) << 4) + (lane & 3);
        const int mb = ((tile & 1) << 5) + (lane >> 2);
        ull acc[4][4];
        #pragma unroll
        for (int a = 0; a < 4; a++)
            #pragma unroll
            for (int bb = 0; bb < 4; bb++) acc[a][bb] = 0ull;
        #pragma unroll
        for (int s = 0; s < 8; s++) {
            const int dd = (ks << 5) + (s << 2);
            ull klo[4], khi[4];
            #pragma unroll
            for (int bb = 0; bb < 4; bb++) {
                ulonglong2 kp = *reinterpret_cast<const ulonglong2*>(sk + (mb + 8 * bb) * 68 + dd);
                klo[bb] = kp.x; khi[bb] = kp.y;
            }
            #pragma unroll
            for (int a = 0; a < 4; a++) {
                ulonglong2 qp = *reinterpret_cast<const ulonglong2*>(sq + (nb + 4 * a) * 68 + dd);
                #pragma unroll
                for (int bb = 0; bb < 4; bb++) {
                    FMAX2(acc[a][bb], qp.x, klo[bb]);
                    FMAX2(acc[a][bb], qp.y, khi[bb]);
                }
            }
        }
        float sc[4][4];
        #pragma unroll
        for (int a = 0; a < 4; a++)
            #pragma unroll
            for (int bb = 0; bb < 4; bb++) {
                float lo, hi; upk(acc[a][bb], lo, hi); sc[a][bb] = lo + hi;
            }
        if (ks == 1) {
            #pragma unroll
            for (int a = 0; a < 4; a++)
                #pragma unroll
                for (int bb = 0; bb < 4; bb++)
                    sat[(nb + 4 * a) * 68 + mb + 8 * bb] = sc[a][bb];
        }
        __syncthreads();
        if (ks == 0) {
            #pragma unroll
            for (int a = 0; a < 4; a++) {
                const int n = nb + 4 * a;
                #pragma unroll
                for (int bb = 0; bb < 4; bb++) {
                    const int m = mb + 8 * bb;
                    float r = (sc[a][bb] + sat[n * 68 + m]) * 0.125f;
                    if (n == m) r = NEG_INF;
                    sat[n * 68 + m] = r;
                }
            }
        }
        __syncthreads();
    }

    // ---------------- Phase C1b: softmax (warp per 4 rows) ----------------
    {
        #pragma unroll
        for (int rr = 0; rr < 4; rr++) {
            int n = (wid << 2) + rr;
            float s0 = sat[n * 68 + lane];
            float s1 = sat[n * 68 + lane + 32];
            float mx = wmax32(fmaxf(s0, s1));
            float e0 = __expf(s0 - mx), e1 = __expf(s1 - mx);
            float inv = 1.f / wsum32(e0 + e1);
            float a0 = e0 * inv, a1 = e1 * inv;
            sat[n * 68 + lane]      = a0;
            sat[n * 68 + lane + 32] = a1;
            size_t tk = (size_t)(b * NN + n) * 64;
            out_attn[tk + lane]      = a0;
            out_attn[tk + lane + 32] = a1;
        }
    }
    __syncthreads();

    // ---------------- Phase C2: clat = attn @ v; same tiling, 2-warp m-split ----------------
    {
        const int tile = wid >> 1, ks = wid & 1;
        const int nb = ((tile >> 1) << 4) + (lane & 3);
        const int d0 = ((tile & 1) << 5) + ((lane >> 2) << 2);
        ull acc[4][2];
        #pragma unroll
        for (int a = 0; a < 4; a++) { acc[a][0] = 0ull; acc[a][1] = 0ull; }
        #pragma unroll
        for (int s = 0; s < 8; s++) {
            const int mm = (ks << 5) + (s << 2);
            ull vlo[4], vhi[4];
            #pragma unroll
            for (int t = 0; t < 4; t++) {
                ulonglong2 vp = *reinterpret_cast<const ulonglong2*>(sv + (mm + t) * 68 + d0);
                vlo[t] = vp.x; vhi[t] = vp.y;
            }
            #pragma unroll
            for (int a = 0; a < 4; a++) {
                float4 a4 = *reinterpret_cast<const float4*>(sat + (nb + 4 * a) * 68 + mm);
                ull a0 = pk(a4.x, a4.x), a1 = pk(a4.y, a4.y);
                ull a2 = pk(a4.z, a4.z), a3 = pk(a4.w, a4.w);
                FMAX2(acc[a][0], a0, vlo[0]); FMAX2(acc[a][1], a0, vhi[0]);
                FMAX2(acc[a][0], a1, vlo[1]); FMAX2(acc[a][1], a1, vhi[1]);
                FMAX2(acc[a][0], a2, vlo[2]); FMAX2(acc[a][1], a2, vhi[2]);
                FMAX2(acc[a][0], a3, vlo[3]); FMAX2(acc[a][1], a3, vhi[3]);
            }
        }
        if (ks == 1) {
            #pragma unroll
            for (int a = 0; a < 4; a++) {
                float x0, x1, x2, x3;
                upk(acc[a][0], x0, x1); upk(acc[a][1], x2, x3);
                *reinterpret_cast<float4*>(sclat + (nb + 4 * a) * 68 + d0) =
                    make_float4(x0, x1, x2, x3);
            }
        }
        __syncthreads();
        if (ks == 0) {
            #pragma unroll
            for (int a = 0; a < 4; a++) {
                float4 p = *reinterpret_cast<const float4*>(sclat + (nb + 4 * a) * 68 + d0);
                float x0, x1, x2, x3;
                upk(acc[a][0], x0, x1); upk(acc[a][1], x2, x3);
                *reinterpret_cast<float4*>(sclat + (nb + 4 * a) * 68 + d0) =
                    make_float4(x0 + p.x, x1 + p.y, x2 + p.z, x3 + p.w);
            }
        }
        __syncthreads();
    }

    // ---------------- Phase C3: rank-4 output projection (warp per token, od_up hoisted) ----------------
    {
        const float4* odd4 = reinterpret_cast<const float4*>(od_down);
        float4 o0 = __ldg(odd4 + lane);
        float4 o1 = __ldg(odd4 + lane + 32);
        float ou[16];
        #pragma unroll
        for (int r = 0; r < 4; r++)
            #pragma unroll
            for (int s = 0; s < 4; s++)
                ou[r * 4 + s] = __ldg(od_up + r * 128 + lane + (s << 5));
        for (int c0 = 0; c0 < 4; c0++) {
            int t = (wid << 2) + c0;
            float ca = sclat[t * 68 + lane];
            float cb = sclat[t * 68 + lane + 32];
            float r0 = wsum32(ca * o0.x + cb * o1.x);
            float r1 = wsum32(ca * o0.y + cb * o1.y);
            float r2 = wsum32(ca * o0.z + cb * o1.z);
            float r3 = wsum32(ca * o0.w + cb * o1.w);
            size_t tk = (size_t)(b * NN + t) * 128;
            #pragma unroll
            for (int s = 0; s < 4; s++) {
                int j = lane + (s << 5);
                float cv = 0.25f * (r0 * ou[s] + r1 * ou[4 + s] + r2 * ou[8 + s] + r3 * ou[12 + s]);
                sh_c[t * 132 + j] = cv;
                out_c[tk + j] = cv;
            }
        }
    }
    __syncthreads();

    // ---------------- Phase D: gate/cand matmuls; h streamed via smem chunks ----------------
    {
        const int ip   = wid & 3;
        const int tile = wid >> 2;
        const int th   = tile >> 1;
        const int j0   = (tile & 1) * 16 + (lane >> 3) * 4;   // 0..31
        const int t0   = th * 32 + (lane & 7);                // + 8c -> 4 tokens
        const float* wsel = (j0 < 16) ? ug_w : cand_w;
        const int j4 = (j0 & 15) >> 2;
        ull acc[4][2];
        #pragma unroll
        for (int c = 0; c < 4; c++) { acc[c][0] = 0ull; acc[c][1] = 0ull; }

        // h part: 4 staged chunks of 64 cols through hst (= dead sk)
        const int r2 = lane >> 4, c4 = lane & 15;
        #pragma unroll
        for (int ch = 0; ch < 4; ch++) {
            #pragma unroll
            for (int rr = 0; rr < 2; rr++) {
                int row = (wid << 2) + (rr << 1) + r2;
                float4 v4 = __ldg(hb4 + row * 64 + (ch << 4) + c4);
                *reinterpret_cast<float4*>(hst + row * 68 + (c4 << 2)) = v4;
            }
            __syncthreads();
            d_accum(hst + t0 * 68 + ip * 16, 68, wsel, 16 + (ch << 6) + ip * 16, 4, j4, acc);
            __syncthreads();
        }
        // z part (i 0..15) and c part (i 272..399), split 4 ways by ip
        d_accum(sh_z + t0 * 20 + ip * 4, 20, wsel, ip * 4, 1, j4, acc);
        d_accum(sh_c + t0 * 132 + ip * 32, 132, wsel, 272 + ip * 32, 8, j4, acc);

        float f[4][4];
        #pragma unroll
        for (int c = 0; c < 4; c++) {
            upk(acc[c][0], f[c][0], f[c][1]);
            upk(acc[c][1], f[c][2], f[c][3]);
        }
        // reduction: sred tiles 0,1 in sq (dead), tiles 2,3 in sv (dead)
        float* srb = ((tile < 2) ? sq : sv) + ((tile & 1) * 3) * 512;
        if (ip != 0) {
            float* dst = srb + (ip - 1) * 512;
            #pragma unroll
            for (int c = 0; c < 4; c++)
                #pragma unroll
                for (int d = 0; d < 4; d++)
                    dst[(c * 4 + d) * 32 + lane] = f[c][d];
        }
        __syncthreads();
        if (ip == 0) {
            #pragma unroll
            for (int s = 0; s < 3; s++) {
                const float* src = srb + s * 512;
                #pragma unroll
                for (int c = 0; c < 4; c++)
                    #pragma unroll
                    for (int d = 0; d < 4; d++)
                        f[c][d] += src[(c * 4 + d) * 32 + lane];
            }
            #pragma unroll
            for (int d = 0; d < 4; d++) {
                int j = j0 + d;
                float bias = (j < 16) ? __ldg(ug_b + j) : __ldg(cand_b + j - 16);
                #pragma unroll
                for (int c = 0; c < 4; c++)
                    sgc[(t0 + 8 * c) * 33 + j] = f[c][d] + bias;
            }
        }
    }
    __syncthreads();

    // ---------------- Phase E: gated update + layernorm ----------------
    {
        const float eta = 1.f / (1.f + __expf(-__ldg(eta_logit)));
        const int s = lane >> 4;
        const int j = lane & 15;
        #pragma unroll
        for (int p = 0; p < 2; p++) {
            int t = (wid << 2) + (p << 1) + s;
            float gp = sgc[t * 33 + j];
            float cp = sgc[t * 33 + 16 + j];
            float eg = eta * (1.f / (1.f + __expf(-gp)));
            float val = (1.f - eg) * sh_z[t * 20 + j] + eg * tanhf(cp);
            float sum = val;
            #pragma unroll
            for (int msk = 8; msk > 0; msk >>= 1)
                sum += __shfl_xor_sync(0xffffffffu, sum, msk, 16);
            float mu = sum * (1.f / 16.f);
            float dv = val - mu;
            float vs = dv * dv;
            #pragma unroll
            for (int msk = 8; msk > 0; msk >>= 1)
                vs += __shfl_xor_sync(0xffffffffu, vs, msk, 16);
            float var = vs * (1.f / 16.f);
            out_z[(size_t)(b * NN + t) * 16 + j] = dv * rsqrtf(var + 1e-5f);
        }
    }
}

extern "C" void kernel_launch(void* const* d_in, const int* in_sizes, int n_in,
                              void* d_out, int out_size) {
    const float* h        = (const float*)d_in[0];
    const float* u        = (const float*)d_in[1];
    const float* z        = (const float*)d_in[2];
    const float* qd_down  = (const float*)d_in[3];
    const float* qd_up    = (const float*)d_in[4];
    const float* kd_down  = (const float*)d_in[5];
    const float* kd_up    = (const float*)d_in[6];
    const float* vd_down  = (const float*)d_in[7];
    const float* vd_up    = (const float*)d_in[8];
    const float* od_down  = (const float*)d_in[9];
    const float* od_up    = (const float*)d_in[10];
    const float* ug_w     = (const float*)d_in[11];
    const float* ug_b     = (const float*)d_in[12];
    const float* cand_w   = (const float*)d_in[13];
    const float* cand_b   = (const float*)d_in[14];
    const float* eta_logit= (const float*)d_in[15];

    float* o = (float*)d_out;
    float* out_c    = o;                        // 4096*64*128
    float* out_z    = o + (size_t)33554432;     // 4096*64*16
    float* out_attn = o + (size_t)37748736;     // 4096*64*64
    float* out_q    = o + (size_t)54525952;
    float* out_k    = o + (size_t)71303168;
    float* out_v    = o + (size_t)88080384;

    const int smem_bytes = SMEM_FLOATS * sizeof(float);  // 108544
    cudaFuncSetAttribute(memetic_fused_kernel,
                         cudaFuncAttributeMaxDynamicSharedMemorySize, smem_bytes);

    memetic_fused_kernel<<<BB, 512, smem_bytes>>>(
        h, u, z, qd_down, qd_up, kd_down, kd_up, vd_down, vd_up,
        od_down, od_up, ug_w, ug_b, cand_w, cand_b, eta_logit,
        out_c, out_z, out_attn, out_q, out_k, out_v);
}

// round 16
// speedup vs baseline: 1.5018x; 1.0341x over previous
#include <cuda_runtime.h>
#include <math.h>

#define BB 4096
#define NN 64

// Per-CTA smem (floats), 108,544 bytes -> 2 CTAs/SM:
//  sh_z [64][20]  = 1280
//  sh_c [64][132] = 8448
//  sq   [64][68]  = 4352  q -> clat (C2) -> h staging lo / sred (D)
//  sk   [64][68]  = 4352  k -> h staging hi / sred (D)
//  sv   [64][68]  = 4352  v
//  sat  [64][68]  = 4352  scores/attn -> gate/cand (D/E)
#define OFF_Z   0
#define OFF_C   1280
#define OFF_Q   9728
#define OFF_K   14080
#define OFF_V   18432
#define OFF_AT  22784
#define SMEM_FLOATS 27136

typedef unsigned long long ull;

__device__ __forceinline__ ull pk(float a, float b) {
    ull r; asm("mov.b64 %0, {%1, %2};" : "=l"(r) : "f"(a), "f"(b)); return r;
}
__device__ __forceinline__ void upk(ull v, float& a, float& b) {
    asm("mov.b64 {%0, %1}, %2;" : "=f"(a), "=f"(b) : "l"(v));
}
#define FMAX2(acc, a, b) asm("fma.rn.f32x2 %0, %1, %2, %0;" : "+l"(acc) : "l"(a), "l"(b))

__device__ __forceinline__ float wsum32(float v) {
    #pragma unroll
    for (int m = 16; m > 0; m >>= 1) v += __shfl_xor_sync(0xffffffffu, v, m);
    return v;
}
__device__ __forceinline__ float wmax32(float v) {
    #pragma unroll
    for (int m = 16; m > 0; m >>= 1) v = fmaxf(v, __shfl_xor_sync(0xffffffffu, v, m));
    return v;
}

// Phase-D inner: 4 tokens (delta-8 rows, smem x) x 16 outputs over n4*4 k-rows; w via LDG.
__device__ __forceinline__ void d_accum(const float* __restrict__ x0, int xs,
                                        const float* __restrict__ wsel, int ibase,
                                        int n4, int j4, ull acc[4][2]) {
    for (int s = 0; s < n4; s++) {
        const int il = s << 2;
        float4 x4[4];
        #pragma unroll
        for (int c = 0; c < 4; c++)
            x4[c] = *reinterpret_cast<const float4*>(x0 + c * 8 * xs + il);
        const float4* wr = reinterpret_cast<const float4*>(wsel + (ibase + il) * 16) + j4;
        #pragma unroll
        for (int r = 0; r < 4; r++) {
            float4 w4 = __ldg(wr + r * 4);
            ull wlo = pk(w4.x, w4.y), whi = pk(w4.z, w4.w);
            #pragma unroll
            for (int c = 0; c < 4; c++) {
                float xv = (r == 0) ? x4[c].x : (r == 1) ? x4[c].y : (r == 2) ? x4[c].z : x4[c].w;
                ull xd = pk(xv, xv);
                FMAX2(acc[c][0], xd, wlo);
                FMAX2(acc[c][1], xd, whi);
            }
        }
    }
}

__global__ __launch_bounds__(512, 2)
void memetic_fused_kernel(
    const float* __restrict__ h, const float* __restrict__ u, const float* __restrict__ z,
    const float* __restrict__ qd_down, const float* __restrict__ qd_up,
    const float* __restrict__ kd_down, const float* __restrict__ kd_up,
    const float* __restrict__ vd_down, const float* __restrict__ vd_up,
    const float* __restrict__ od_down, const float* __restrict__ od_up,
    const float* __restrict__ ug_w, const float* __restrict__ ug_b,
    const float* __restrict__ cand_w, const float* __restrict__ cand_b,
    const float* __restrict__ eta_logit,
    float* __restrict__ out_c, float* __restrict__ out_z,
    float* __restrict__ out_attn, float* __restrict__ out_q,
    float* __restrict__ out_k, float* __restrict__ out_v)
{
    extern __shared__ float sm[];
    float* sh_z = sm + OFF_Z;
    float* sh_c = sm + OFF_C;
    float* sq   = sm + OFF_Q;
    float* sk   = sm + OFF_K;
    float* sv   = sm + OFF_V;
    float* sat  = sm + OFF_AT;
    float* sclat = sq;           // alias: q dead after C1
    float* hst   = sq;           // alias: sq+sk contiguous, h staging [64][132] in D
    float* sred  = sq;           // alias: reduction scratch after staging done
    float* sgc   = sat;          // alias: at dead after C2

    const int b    = blockIdx.x;
    const int tid  = threadIdx.x;
    const int wid  = tid >> 5;
    const int lane = tid & 31;
    const float NEG_INF = __int_as_float(0xff800000);
    const float* hb = h + (size_t)b * (NN * 256);
    const float4* hb4 = reinterpret_cast<const float4*>(hb);

    // ---------------- Phase A: stage z ----------------
    {
        const float* zb = z + (size_t)b * (NN * 16);
        for (int i = tid; i < NN * 16; i += 512)
            sh_z[(i >> 4) * 20 + (i & 15)] = zb[i];
    }
    __syncthreads();

    // ---------------- Phase B (warp-specialized): q warps 0-7, k warps 8-11, v warps 12-15 ----
    if (wid < 8) {
        const float4* qdd4 = reinterpret_cast<const float4*>(qd_down);
        float4 qw[8];
        #pragma unroll
        for (int it = 0; it < 8; it++) qw[it] = __ldg(qdd4 + lane + it * 32);
        float4 qwz = make_float4(0.f, 0.f, 0.f, 0.f);
        if (lane < 16) qwz = __ldg(qdd4 + 256 + lane);
        float2 qu2[4];
        #pragma unroll
        for (int r = 0; r < 4; r++)
            qu2[r] = __ldg(reinterpret_cast<const float2*>(qd_up + r * 64) + lane);
        for (int c0 = 0; c0 < 8; c0++) {
            const int t = (wid << 3) + c0;
            const float* hrow = hb + t * 256;
            float xz = (lane < 16) ? sh_z[t * 20 + lane] : 0.f;
            float q0 = xz * qwz.x, q1 = xz * qwz.y, q2 = xz * qwz.z, q3 = xz * qwz.w;
            #pragma unroll
            for (int it = 0; it < 8; it++) {
                float x = __ldg(hrow + lane + it * 32);
                q0 += x * qw[it].x; q1 += x * qw[it].y; q2 += x * qw[it].z; q3 += x * qw[it].w;
            }
            q0 = wsum32(q0); q1 = wsum32(q1); q2 = wsum32(q2); q3 = wsum32(q3);
            const size_t tok = (size_t)(b * NN + t);
            float2 qv;
            qv.x = 0.25f * (q0 * qu2[0].x + q1 * qu2[1].x + q2 * qu2[2].x + q3 * qu2[3].x);
            qv.y = 0.25f * (q0 * qu2[0].y + q1 * qu2[1].y + q2 * qu2[2].y + q3 * qu2[3].y);
            *reinterpret_cast<float2*>(sq + t * 68 + 2 * lane) = qv;
            *reinterpret_cast<float2*>(out_q + tok * 64 + 2 * lane) = qv;
        }
    } else if (wid < 12) {
        const float* ub = u + (size_t)b * (NN * 128);
        const float4* kdd4 = reinterpret_cast<const float4*>(kd_down);
        float4 kw4[4];
        #pragma unroll
        for (int it = 0; it < 4; it++) kw4[it] = __ldg(kdd4 + lane + it * 32);
        float2 ku2[4];
        #pragma unroll
        for (int r = 0; r < 4; r++)
            ku2[r] = __ldg(reinterpret_cast<const float2*>(kd_up + r * 64) + lane);
        const int w2 = wid - 8;
        for (int c0 = 0; c0 < 16; c0++) {
            const int t = (w2 << 4) + c0;
            float k0 = 0.f, k1 = 0.f, k2 = 0.f, k3 = 0.f;
            #pragma unroll
            for (int it = 0; it < 4; it++) {
                float x = __ldg(ub + t * 128 + lane + it * 32);
                k0 += x * kw4[it].x; k1 += x * kw4[it].y; k2 += x * kw4[it].z; k3 += x * kw4[it].w;
            }
            k0 = wsum32(k0); k1 = wsum32(k1); k2 = wsum32(k2); k3 = wsum32(k3);
            const size_t tok = (size_t)(b * NN + t);
            float2 kv;
            kv.x = 0.25f * (k0 * ku2[0].x + k1 * ku2[1].x + k2 * ku2[2].x + k3 * ku2[3].x);
            kv.y = 0.25f * (k0 * ku2[0].y + k1 * ku2[1].y + k2 * ku2[2].y + k3 * ku2[3].y);
            *reinterpret_cast<float2*>(sk + t * 68 + 2 * lane) = kv;
            *reinterpret_cast<float2*>(out_k + tok * 64 + 2 * lane) = kv;
        }
    } else {
        const float* ub = u + (size_t)b * (NN * 128);
        const float4* vdd4 = reinterpret_cast<const float4*>(vd_down);
        float4 vw4[4];
        #pragma unroll
        for (int it = 0; it < 4; it++) vw4[it] = __ldg(vdd4 + lane + it * 32);
        float2 vu2[4];
        #pragma unroll
        for (int r = 0; r < 4; r++)
            vu2[r] = __ldg(reinterpret_cast<const float2*>(vd_up + r * 64) + lane);
        const int w2 = wid - 12;
        for (int c0 = 0; c0 < 16; c0++) {
            const int t = (w2 << 4) + c0;
            float v0 = 0.f, v1 = 0.f, v2 = 0.f, v3 = 0.f;
            #pragma unroll
            for (int it = 0; it < 4; it++) {
                float x = __ldg(ub + t * 128 + lane + it * 32);
                v0 += x * vw4[it].x; v1 += x * vw4[it].y; v2 += x * vw4[it].z; v3 += x * vw4[it].w;
            }
            v0 = wsum32(v0); v1 = wsum32(v1); v2 = wsum32(v2); v3 = wsum32(v3);
            const size_t tok = (size_t)(b * NN + t);
            float2 vv;
            vv.x = 0.25f * (v0 * vu2[0].x + v1 * vu2[1].x + v2 * vu2[2].x + v3 * vu2[3].x);
            vv.y = 0.25f * (v0 * vu2[0].y + v1 * vu2[1].y + v2 * vu2[2].y + v3 * vu2[3].y);
            *reinterpret_cast<float2*>(sv + t * 68 + 2 * lane) = vv;
            *reinterpret_cast<float2*>(out_v + tok * 64 + 2 * lane) = vv;
        }
    }
    __syncthreads();

    // ---------------- Phase C1: QK scores; 16n x 32m tiles, thread 4x4, 2-warp d-split ----------------
    {
        const int tile = wid >> 1, ks = wid & 1;
        const int nb = ((tile >> 1) << 4) + (lane & 3);
        const int mb = ((tile & 1) << 5) + (lane >> 2);
        ull acc[4][4];
        #pragma unroll
        for (int a = 0; a < 4; a++)
            #pragma unroll
            for (int bb = 0; bb < 4; bb++) acc[a][bb] = 0ull;
        #pragma unroll
        for (int s = 0; s < 8; s++) {
            const int dd = (ks << 5) + (s << 2);
            ull klo[4], khi[4];
            #pragma unroll
            for (int bb = 0; bb < 4; bb++) {
                ulonglong2 kp = *reinterpret_cast<const ulonglong2*>(sk + (mb + 8 * bb) * 68 + dd);
                klo[bb] = kp.x; khi[bb] = kp.y;
            }
            #pragma unroll
            for (int a = 0; a < 4; a++) {
                ulonglong2 qp = *reinterpret_cast<const ulonglong2*>(sq + (nb + 4 * a) * 68 + dd);
                #pragma unroll
                for (int bb = 0; bb < 4; bb++) {
                    FMAX2(acc[a][bb], qp.x, klo[bb]);
                    FMAX2(acc[a][bb], qp.y, khi[bb]);
                }
            }
        }
        float sc[4][4];
        #pragma unroll
        for (int a = 0; a < 4; a++)
            #pragma unroll
            for (int bb = 0; bb < 4; bb++) {
                float lo, hi; upk(acc[a][bb], lo, hi); sc[a][bb] = lo + hi;
            }
        if (ks == 1) {
            #pragma unroll
            for (int a = 0; a < 4; a++)
                #pragma unroll
                for (int bb = 0; bb < 4; bb++)
                    sat[(nb + 4 * a) * 68 + mb + 8 * bb] = sc[a][bb];
        }
        __syncthreads();
        if (ks == 0) {
            #pragma unroll
            for (int a = 0; a < 4; a++) {
                const int n = nb + 4 * a;
                #pragma unroll
                for (int bb = 0; bb < 4; bb++) {
                    const int m = mb + 8 * bb;
                    float r = (sc[a][bb] + sat[n * 68 + m]) * 0.125f;
                    if (n == m) r = NEG_INF;
                    sat[n * 68 + m] = r;
                }
            }
        }
        __syncthreads();
    }

    // ---------------- Phase C1b: softmax (warp per 4 rows, float2 lanes) ----------------
    {
        #pragma unroll
        for (int rr = 0; rr < 4; rr++) {
            int n = (wid << 2) + rr;
            float2 s01 = *reinterpret_cast<const float2*>(sat + n * 68 + 2 * lane);
            float mx = wmax32(fmaxf(s01.x, s01.y));
            float e0 = __expf(s01.x - mx), e1 = __expf(s01.y - mx);
            float inv = 1.f / wsum32(e0 + e1);
            float2 a01 = make_float2(e0 * inv, e1 * inv);
            *reinterpret_cast<float2*>(sat + n * 68 + 2 * lane) = a01;
            size_t tk = (size_t)(b * NN + n) * 64;
            *reinterpret_cast<float2*>(out_attn + tk + 2 * lane) = a01;
        }
    }
    __syncthreads();

    // ---------------- Phase C2: clat = attn @ v; same tiling, 2-warp m-split ----------------
    {
        const int tile = wid >> 1, ks = wid & 1;
        const int nb = ((tile >> 1) << 4) + (lane & 3);
        const int d0 = ((tile & 1) << 5) + ((lane >> 2) << 2);
        ull acc[4][2];
        #pragma unroll
        for (int a = 0; a < 4; a++) { acc[a][0] = 0ull; acc[a][1] = 0ull; }
        #pragma unroll
        for (int s = 0; s < 8; s++) {
            const int mm = (ks << 5) + (s << 2);
            ull vlo[4], vhi[4];
            #pragma unroll
            for (int t = 0; t < 4; t++) {
                ulonglong2 vp = *reinterpret_cast<const ulonglong2*>(sv + (mm + t) * 68 + d0);
                vlo[t] = vp.x; vhi[t] = vp.y;
            }
            #pragma unroll
            for (int a = 0; a < 4; a++) {
                float4 a4 = *reinterpret_cast<const float4*>(sat + (nb + 4 * a) * 68 + mm);
                ull a0 = pk(a4.x, a4.x), a1 = pk(a4.y, a4.y);
                ull a2 = pk(a4.z, a4.z), a3 = pk(a4.w, a4.w);
                FMAX2(acc[a][0], a0, vlo[0]); FMAX2(acc[a][1], a0, vhi[0]);
                FMAX2(acc[a][0], a1, vlo[1]); FMAX2(acc[a][1], a1, vhi[1]);
                FMAX2(acc[a][0], a2, vlo[2]); FMAX2(acc[a][1], a2, vhi[2]);
                FMAX2(acc[a][0], a3, vlo[3]); FMAX2(acc[a][1], a3, vhi[3]);
            }
        }
        if (ks == 1) {
            #pragma unroll
            for (int a = 0; a < 4; a++) {
                float x0, x1, x2, x3;
                upk(acc[a][0], x0, x1); upk(acc[a][1], x2, x3);
                *reinterpret_cast<float4*>(sclat + (nb + 4 * a) * 68 + d0) =
                    make_float4(x0, x1, x2, x3);
            }
        }
        __syncthreads();
        if (ks == 0) {
            #pragma unroll
            for (int a = 0; a < 4; a++) {
                float4 p = *reinterpret_cast<const float4*>(sclat + (nb + 4 * a) * 68 + d0);
                float x0, x1, x2, x3;
                upk(acc[a][0], x0, x1); upk(acc[a][1], x2, x3);
                *reinterpret_cast<float4*>(sclat + (nb + 4 * a) * 68 + d0) =
                    make_float4(x0 + p.x, x1 + p.y, x2 + p.z, x3 + p.w);
            }
        }
        __syncthreads();
    }

    // ---------------- Phase C3: rank-4 output projection (warp per token, float4 epilogue) --------
    {
        const float4* odd4 = reinterpret_cast<const float4*>(od_down);
        float4 o0 = __ldg(odd4 + lane);
        float4 o1 = __ldg(odd4 + lane + 32);
        float4 ou4[4];
        #pragma unroll
        for (int r = 0; r < 4; r++)
            ou4[r] = __ldg(reinterpret_cast<const float4*>(od_up + r * 128) + lane);
        for (int c0 = 0; c0 < 4; c0++) {
            int t = (wid << 2) + c0;
            float ca = sclat[t * 68 + lane];
            float cb = sclat[t * 68 + lane + 32];
            float r0 = wsum32(ca * o0.x + cb * o1.x);
            float r1 = wsum32(ca * o0.y + cb * o1.y);
            float r2 = wsum32(ca * o0.z + cb * o1.z);
            float r3 = wsum32(ca * o0.w + cb * o1.w);
            size_t tk = (size_t)(b * NN + t) * 128;
            float4 cv;
            cv.x = 0.25f * (r0 * ou4[0].x + r1 * ou4[1].x + r2 * ou4[2].x + r3 * ou4[3].x);
            cv.y = 0.25f * (r0 * ou4[0].y + r1 * ou4[1].y + r2 * ou4[2].y + r3 * ou4[3].y);
            cv.z = 0.25f * (r0 * ou4[0].z + r1 * ou4[1].z + r2 * ou4[2].z + r3 * ou4[3].z);
            cv.w = 0.25f * (r0 * ou4[0].w + r1 * ou4[1].w + r2 * ou4[2].w + r3 * ou4[3].w);
            *reinterpret_cast<float4*>(sh_c + t * 132 + 4 * lane) = cv;
            *reinterpret_cast<float4*>(out_c + tk + 4 * lane) = cv;
        }
    }
    __syncthreads();

    // ---------------- Phase D: gate/cand matmuls; h streamed via 2 big smem chunks ----------------
    {
        const int ip   = wid & 3;
        const int tile = wid >> 2;
        const int th   = tile >> 1;
        const int j0   = (tile & 1) * 16 + (lane >> 3) * 4;   // 0..31
        const int t0   = th * 32 + (lane & 7);                // + 8c -> 4 tokens
        const float* wsel = (j0 < 16) ? ug_w : cand_w;
        const int j4 = (j0 & 15) >> 2;
        ull acc[4][2];
        #pragma unroll
        for (int c = 0; c < 4; c++) { acc[c][0] = 0ull; acc[c][1] = 0ull; }

        // h part: 2 staged chunks of 128 cols through hst (= dead sq+sk, stride 132)
        const int r2 = lane >> 4, c4 = lane & 15;
        #pragma unroll
        for (int ch = 0; ch < 2; ch++) {
            #pragma unroll
            for (int rr = 0; rr < 2; rr++) {
                int row = (wid << 2) + (rr << 1) + r2;
                #pragma unroll
                for (int it = 0; it < 2; it++) {
                    int cc = (it << 4) + c4;
                    float4 v4 = __ldg(hb4 + row * 64 + (ch << 5) + cc);
                    *reinterpret_cast<float4*>(hst + row * 132 + (cc << 2)) = v4;
                }
            }
            __syncthreads();
            d_accum(hst + t0 * 132 + ip * 32, 132, wsel, 16 + (ch << 7) + ip * 32, 8, j4, acc);
            __syncthreads();
        }
        // z part (i 0..15) and c part (i 272..399), split 4 ways by ip
        d_accum(sh_z + t0 * 20 + ip * 4, 20, wsel, ip * 4, 1, j4, acc);
        d_accum(sh_c + t0 * 132 + ip * 32, 132, wsel, 272 + ip * 32, 8, j4, acc);

        float f[4][4];
        #pragma unroll
        for (int c = 0; c < 4; c++) {
            upk(acc[c][0], f[c][0], f[c][1]);
            upk(acc[c][1], f[c][2], f[c][3]);
        }
        // reduction scratch in sred (= sq+sk span, staging done)
        if (ip != 0) {
            float* dst = sred + (tile * 3 + (ip - 1)) * 512;
            #pragma unroll
            for (int c = 0; c < 4; c++)
                #pragma unroll
                for (int d = 0; d < 4; d++)
                    dst[(c * 4 + d) * 32 + lane] = f[c][d];
        }
        __syncthreads();
        if (ip == 0) {
            #pragma unroll
            for (int s = 0; s < 3; s++) {
                const float* src = sred + (tile * 3 + s) * 512;
                #pragma unroll
                for (int c = 0; c < 4; c++)
                    #pragma unroll
                    for (int d = 0; d < 4; d++)
                        f[c][d] += src[(c * 4 + d) * 32 + lane];
            }
            #pragma unroll
            for (int d = 0; d < 4; d++) {
                int j = j0 + d;
                float bias = (j < 16) ? __ldg(ug_b + j) : __ldg(cand_b + j - 16);
                #pragma unroll
                for (int c = 0; c < 4; c++)
                    sgc[(t0 + 8 * c) * 33 + j] = f[c][d] + bias;
            }
        }
    }
    __syncthreads();

    // ---------------- Phase E: gated update + layernorm ----------------
    {
        const float eta = 1.f / (1.f + __expf(-__ldg(eta_logit)));
        const int s = lane >> 4;
        const int j = lane & 15;
        #pragma unroll
        for (int p = 0; p < 2; p++) {
            int t = (wid << 2) + (p << 1) + s;
            float gp = sgc[t * 33 + j];
            float cp = sgc[t * 33 + 16 + j];
            float eg = eta * (1.f / (1.f + __expf(-gp)));
            float val = (1.f - eg) * sh_z[t * 20 + j] + eg * tanhf(cp);
            float sum = val;
            #pragma unroll
            for (int msk = 8; msk > 0; msk >>= 1)
                sum += __shfl_xor_sync(0xffffffffu, sum, msk, 16);
            float mu = sum * (1.f / 16.f);
            float dv = val - mu;
            float vs = dv * dv;
            #pragma unroll
            for (int msk = 8; msk > 0; msk >>= 1)
                vs += __shfl_xor_sync(0xffffffffu, vs, msk, 16);
            float var = vs * (1.f / 16.f);
            out_z[(size_t)(b * NN + t) * 16 + j] = dv * rsqrtf(var + 1e-5f);
        }
    }
}

extern "C" void kernel_launch(void* const* d_in, const int* in_sizes, int n_in,
                              void* d_out, int out_size) {
    const float* h        = (const float*)d_in[0];
    const float* u        = (const float*)d_in[1];
    const float* z        = (const float*)d_in[2];
    const float* qd_down  = (const float*)d_in[3];
    const float* qd_up    = (const float*)d_in[4];
    const float* kd_down  = (const float*)d_in[5];
    const float* kd_up    = (const float*)d_in[6];
    const float* vd_down  = (const float*)d_in[7];
    const float* vd_up    = (const float*)d_in[8];
    const float* od_down  = (const float*)d_in[9];
    const float* od_up    = (const float*)d_in[10];
    const float* ug_w     = (const float*)d_in[11];
    const float* ug_b     = (const float*)d_in[12];
    const float* cand_w   = (const float*)d_in[13];
    const float* cand_b   = (const float*)d_in[14];
    const float* eta_logit= (const float*)d_in[15];

    float* o = (float*)d_out;
    float* out_c    = o;                        // 4096*64*128
    float* out_z    = o + (size_t)33554432;     // 4096*64*16
    float* out_attn = o + (size_t)37748736;     // 4096*64*64
    float* out_q    = o + (size_t)54525952;
    float* out_k    = o + (size_t)71303168;
    float* out_v    = o + (size_t)88080384;

    const int smem_bytes = SMEM_FLOATS * sizeof(float);  // 108544
    cudaFuncSetAttribute(memetic_fused_kernel,
                         cudaFuncAttributeMaxDynamicSharedMemorySize, smem_bytes);

    memetic_fused_kernel<<<BB, 512, smem_bytes>>>(
        h, u, z, qd_down, qd_up, kd_down, kd_up, vd_down, vd_up,
        od_down, od_up, ug_w, ug_b, cand_w, cand_b, eta_logit,
        out_c, out_z, out_attn, out_q, out_k, out_v);
}